// round 2
// baseline (speedup 1.0000x reference)
#include <cuda_runtime.h>
#include <math.h>

#define BATCH   2
#define SEQ     2048
#define DMODEL  2048
#define NHEADS  16
#define DK      128
#define MTOT    (BATCH * SEQ)   // 4096

// ---------------- scratch (device globals: no allocation allowed) ----------------
__device__ float g_q [(size_t)MTOT * DMODEL];
__device__ float g_k [(size_t)MTOT * DMODEL];
__device__ float g_v [(size_t)MTOT * DMODEL];
__device__ float g_ao[(size_t)MTOT * DMODEL];
__device__ float g_cos[SEQ * (DK / 2)];
__device__ float g_sin[SEQ * (DK / 2)];

// ---------------- RoPE table: accurate sin/cos of the fp32 angle ----------------
__global__ void rope_table_kernel(const int* __restrict__ tp) {
    int idx = blockIdx.x * blockDim.x + threadIdx.x;
    if (idx >= SEQ * (DK / 2)) return;
    int s = idx / (DK / 2);
    int i = idx % (DK / 2);
    // match reference: inv_freq computed in fp32, angle = fp32(pos) * fp32(inv_freq)
    float ex   = (float)(2 * i) / (float)DK;
    float invf = 1.0f / powf(10000.0f, ex);
    float angf = (float)tp[s] * invf;
    // reference (XLA) evaluates cos/sin of that fp32 angle accurately -> use fp64
    double a = (double)angf;
    g_cos[idx] = (float)cos(a);
    g_sin[idx] = (float)sin(a);
}

// ---------------- C[M,N] = A[M,K] @ B[N,K]^T  (fp32, optional fused RoPE) -------
// 128x128 block tile, BK=8, 256 threads, 8x8 per thread.
template<bool ROPE>
__global__ __launch_bounds__(256, 2) void gemm_nt(
    const float* __restrict__ A, const float* __restrict__ B,
    float* __restrict__ C, int M, int N, int K)
{
    __shared__ __align__(16) float As[8 * 132];
    __shared__ __align__(16) float Bs[8 * 132];

    const int tid  = threadIdx.x;
    const int row0 = blockIdx.y * 128;
    const int col0 = blockIdx.x * 128;

    // warp/lane tiling: 8 warps as 4x2, each warp 32x64, lanes as 4x8 of 8x8 tiles
    const int w      = tid >> 5;
    const int lane   = tid & 31;
    const int rowOff = (w & 3) * 32 + (lane & 3) * 8;
    const int colOff = (w >> 2) * 64 + (lane >> 2) * 8;

    // tile loaders: one float4 per thread per tile
    const int ldRow = tid >> 1;
    const int ldK   = (tid & 1) * 4;
    const float* Ap = A + (size_t)(row0 + ldRow) * K + ldK;
    const float* Bp = B + (size_t)(col0 + ldRow) * K + ldK;

    float acc[8][8];
#pragma unroll
    for (int i = 0; i < 8; ++i)
#pragma unroll
        for (int j = 0; j < 8; ++j) acc[i][j] = 0.f;

    float4 aNext = *(const float4*)Ap;
    float4 bNext = *(const float4*)Bp;

    for (int kk = 0; kk < K; kk += 8) {
        As[(ldK + 0) * 132 + ldRow] = aNext.x;
        As[(ldK + 1) * 132 + ldRow] = aNext.y;
        As[(ldK + 2) * 132 + ldRow] = aNext.z;
        As[(ldK + 3) * 132 + ldRow] = aNext.w;
        Bs[(ldK + 0) * 132 + ldRow] = bNext.x;
        Bs[(ldK + 1) * 132 + ldRow] = bNext.y;
        Bs[(ldK + 2) * 132 + ldRow] = bNext.z;
        Bs[(ldK + 3) * 132 + ldRow] = bNext.w;
        __syncthreads();

        if (kk + 8 < K) {  // register prefetch of next k-slab
            aNext = *(const float4*)(Ap + kk + 8);
            bNext = *(const float4*)(Bp + kk + 8);
        }

#pragma unroll
        for (int k = 0; k < 8; ++k) {
            float4 a0 = *(const float4*)(As + k * 132 + rowOff);
            float4 a1 = *(const float4*)(As + k * 132 + rowOff + 4);
            float4 b0 = *(const float4*)(Bs + k * 132 + colOff);
            float4 b1 = *(const float4*)(Bs + k * 132 + colOff + 4);
            float ar[8] = {a0.x, a0.y, a0.z, a0.w, a1.x, a1.y, a1.z, a1.w};
            float br[8] = {b0.x, b0.y, b0.z, b0.w, b1.x, b1.y, b1.z, b1.w};
#pragma unroll
            for (int i = 0; i < 8; ++i)
#pragma unroll
                for (int j = 0; j < 8; ++j)
                    acc[i][j] += ar[i] * br[j];
        }
        __syncthreads();
    }

#pragma unroll
    for (int i = 0; i < 8; ++i) {
        int r = row0 + rowOff + i;
        float out[8];
#pragma unroll
        for (int j = 0; j < 8; ++j) out[j] = acc[i][j];
        if (ROPE) {
            int pos = r & (SEQ - 1);
#pragma unroll
            for (int jp = 0; jp < 8; jp += 2) {
                int col = col0 + colOff + jp;
                int pr  = (col & (DK - 1)) >> 1;
                float cs = g_cos[pos * (DK / 2) + pr];
                float sn = g_sin[pos * (DK / 2) + pr];
                float x1 = out[jp], x2 = out[jp + 1];
                out[jp]     = x1 * cs - x2 * sn;
                out[jp + 1] = x1 * sn + x2 * cs;
            }
        }
        float* Cp = C + (size_t)r * N + col0 + colOff;
        *(float4*)(Cp)     = make_float4(out[0], out[1], out[2], out[3]);
        *(float4*)(Cp + 4) = make_float4(out[4], out[5], out[6], out[7]);
    }
}

// ---------------- causal flash attention, fp32, Bq=Bk=64, Dk=128 ----------------
// 256 threads: ty=tid/16 owns 4 q-rows, tx=tid%16.
// S tile: thread computes s[4][4] for k columns (tx + 16*j).
// O tile: thread owns O[4][8] for d columns (tx + 16*jd).
__global__ __launch_bounds__(256) void attn_kernel(
    const float* __restrict__ Q, const float* __restrict__ Kg,
    const float* __restrict__ Vg, float* __restrict__ Og)
{
    extern __shared__ __align__(16) float sm[];
    float* Qs = sm;                 // 64 x 132
    float* Ks = Qs + 64 * 132;      // 64 x 132
    float* Vs = Ks + 64 * 132;      // 64 x 128
    float* Ps = Vs + 64 * 128;      // 64 x 68

    const int tid = threadIdx.x;
    const int tx  = tid & 15;
    const int ty  = tid >> 4;
    const int qb  = blockIdx.x;
    const int bh  = blockIdx.y;
    const int b   = bh >> 4;
    const int h   = bh & 15;
    const int q0  = qb * 64;
    const size_t base = (size_t)b * SEQ * DMODEL + (size_t)h * DK;

    // load Q tile
    for (int f = tid; f < 64 * 32; f += 256) {
        int r = f >> 5, c4 = (f & 31) << 2;
        *(float4*)(Qs + r * 132 + c4) =
            *(const float4*)(Q + base + (size_t)(q0 + r) * DMODEL + c4);
    }

    float m_i[4], l_i[4], O[4][8];
#pragma unroll
    for (int i = 0; i < 4; ++i) {
        m_i[i] = -1e30f;
        l_i[i] = 0.f;
#pragma unroll
        for (int jd = 0; jd < 8; ++jd) O[i][jd] = 0.f;
    }
    const float scale = 0.08838834764831845f;  // 1/sqrt(128)

    for (int kb = 0; kb <= qb; ++kb) {
        const int k0 = kb * 64;
        __syncthreads();  // prior P@V done before overwriting K/V
        for (int f = tid; f < 64 * 32; f += 256) {
            int r = f >> 5, c4 = (f & 31) << 2;
            *(float4*)(Ks + r * 132 + c4) =
                *(const float4*)(Kg + base + (size_t)(k0 + r) * DMODEL + c4);
            *(float4*)(Vs + r * 128 + c4) =
                *(const float4*)(Vg + base + (size_t)(k0 + r) * DMODEL + c4);
        }
        __syncthreads();

        float s[4][4];
#pragma unroll
        for (int i = 0; i < 4; ++i)
#pragma unroll
            for (int j = 0; j < 4; ++j) s[i][j] = 0.f;

#pragma unroll 8
        for (int d4 = 0; d4 < 32; ++d4) {
            float4 kvv[4], qvv[4];
#pragma unroll
            for (int j = 0; j < 4; ++j)
                kvv[j] = *(const float4*)(Ks + (tx + 16 * j) * 132 + 4 * d4);
#pragma unroll
            for (int i = 0; i < 4; ++i)
                qvv[i] = *(const float4*)(Qs + (ty * 4 + i) * 132 + 4 * d4);
#pragma unroll
            for (int i = 0; i < 4; ++i)
#pragma unroll
                for (int j = 0; j < 4; ++j)
                    s[i][j] += qvv[i].x * kvv[j].x + qvv[i].y * kvv[j].y +
                               qvv[i].z * kvv[j].z + qvv[i].w * kvv[j].w;
        }

        const bool diag = (kb == qb);
#pragma unroll
        for (int i = 0; i < 4; ++i) {
            const int qg = q0 + ty * 4 + i;
            float mx = -1e30f;
#pragma unroll
            for (int j = 0; j < 4; ++j) {
                float sv = s[i][j] * scale;
                if (diag && (k0 + tx + 16 * j > qg)) sv = -1e30f;
                s[i][j] = sv;
                mx = fmaxf(mx, sv);
            }
#pragma unroll
            for (int off = 8; off > 0; off >>= 1)
                mx = fmaxf(mx, __shfl_xor_sync(0xffffffffu, mx, off));

            float mnew  = fmaxf(m_i[i], mx);
            float alpha = __expf(m_i[i] - mnew);
            float psum  = 0.f;
#pragma unroll
            for (int j = 0; j < 4; ++j) {
                float p = __expf(s[i][j] - mnew);
                Ps[(ty * 4 + i) * 68 + tx + 16 * j] = p;
                psum += p;
            }
#pragma unroll
            for (int off = 8; off > 0; off >>= 1)
                psum += __shfl_xor_sync(0xffffffffu, psum, off);

            l_i[i] = l_i[i] * alpha + psum;
            m_i[i] = mnew;
#pragma unroll
            for (int jd = 0; jd < 8; ++jd) O[i][jd] *= alpha;
        }
        __syncthreads();

        // O += P @ V
#pragma unroll 4
        for (int kk = 0; kk < 64; ++kk) {
            float pv[4];
#pragma unroll
            for (int i = 0; i < 4; ++i) pv[i] = Ps[(ty * 4 + i) * 68 + kk];
#pragma unroll
            for (int jd = 0; jd < 8; ++jd) {
                float vv = Vs[kk * 128 + tx + 16 * jd];
#pragma unroll
                for (int i = 0; i < 4; ++i) O[i][jd] += pv[i] * vv;
            }
        }
    }

#pragma unroll
    for (int i = 0; i < 4; ++i) {
        float inv = 1.0f / l_i[i];
        size_t rowb = ((size_t)b * SEQ + q0 + ty * 4 + i) * DMODEL + (size_t)h * DK;
#pragma unroll
        for (int jd = 0; jd < 8; ++jd)
            Og[rowb + tx + 16 * jd] = O[i][jd] * inv;
    }
}

// ---------------------------------------------------------------------------------
extern "C" void kernel_launch(void* const* d_in, const int* in_sizes, int n_in,
                              void* d_out, int out_size)
{
    const float* x  = (const float*)d_in[0];
    const int*   tp = (const int*)  d_in[1];
    const float* wq = (const float*)d_in[2];
    const float* wk = (const float*)d_in[3];
    const float* wv = (const float*)d_in[4];
    const float* wo = (const float*)d_in[5];
    float* out = (float*)d_out;

    float *qp, *kp, *vp, *aop;
    cudaGetSymbolAddress((void**)&qp,  g_q);
    cudaGetSymbolAddress((void**)&kp,  g_k);
    cudaGetSymbolAddress((void**)&vp,  g_v);
    cudaGetSymbolAddress((void**)&aop, g_ao);

    rope_table_kernel<<<(SEQ * (DK / 2) + 255) / 256, 256>>>(tp);

    dim3 gg(DMODEL / 128, MTOT / 128);
    gemm_nt<true ><<<gg, 256>>>(x, wq, qp, MTOT, DMODEL, DMODEL);
    gemm_nt<true ><<<gg, 256>>>(x, wk, kp, MTOT, DMODEL, DMODEL);
    gemm_nt<false><<<gg, 256>>>(x, wv, vp, MTOT, DMODEL, DMODEL);

    const int ATTN_SMEM = (64 * 132 + 64 * 132 + 64 * 128 + 64 * 68) * 4;
    cudaFuncSetAttribute(attn_kernel, cudaFuncAttributeMaxDynamicSharedMemorySize,
                         ATTN_SMEM);
    attn_kernel<<<dim3(SEQ / 64, BATCH * NHEADS), 256, ATTN_SMEM>>>(qp, kp, vp, aop);

    gemm_nt<false><<<gg, 256>>>(aop, wo, out, MTOT, DMODEL, DMODEL);
}

// round 4
// speedup vs baseline: 1.5833x; 1.5833x over previous
#include <cuda_runtime.h>
#include <cuda_bf16.h>
#include <math.h>
#include <stdint.h>

#define BATCH   2
#define SEQ     2048
#define DMODEL  2048
#define NHEADS  16
#define DK      128
#define MTOT    (BATCH * SEQ)   // 4096
#define KC      64
#define NST     (DMODEL / KC)   // 32
#define STAGE_B 65536

// ---------------- scratch ----------------
__device__ float g_q [(size_t)MTOT * DMODEL];
__device__ float g_k [(size_t)MTOT * DMODEL];
__device__ float g_v [(size_t)MTOT * DMODEL];
__device__ float g_ao[(size_t)MTOT * DMODEL];
__device__ float g_cos[SEQ * (DK / 2)];
__device__ float g_sin[SEQ * (DK / 2)];
__device__ __nv_bfloat16 g_xHi [(size_t)MTOT * DMODEL];
__device__ __nv_bfloat16 g_xLo [(size_t)MTOT * DMODEL];
__device__ __nv_bfloat16 g_aoHi[(size_t)MTOT * DMODEL];
__device__ __nv_bfloat16 g_aoLo[(size_t)MTOT * DMODEL];
__device__ __nv_bfloat16 g_wHi [(size_t)4 * DMODEL * DMODEL];
__device__ __nv_bfloat16 g_wLo [(size_t)4 * DMODEL * DMODEL];

// ---------------- PTX helpers (all sm_80-era: legal on compute_103 base) --------
__device__ __forceinline__ uint32_t smem_u32(const void* p) {
    uint32_t a;
    asm("{ .reg .u64 t; cvta.to.shared.u64 t, %1; cvt.u32.u64 %0, t; }" : "=r"(a) : "l"(p));
    return a;
}
__device__ __forceinline__ void cpa16(uint32_t dst, const void* src) {
    asm volatile("cp.async.cg.shared.global [%0], [%1], 16;" :: "r"(dst), "l"(src) : "memory");
}
__device__ __forceinline__ void cpa_commit() {
    asm volatile("cp.async.commit_group;" ::: "memory");
}
__device__ __forceinline__ void cpa_wait1() {
    asm volatile("cp.async.wait_group 1;" ::: "memory");
}
__device__ __forceinline__ void cpa_wait0() {
    asm volatile("cp.async.wait_group 0;" ::: "memory");
}
__device__ __forceinline__ void ldsm4(uint32_t* r, uint32_t addr) {
    asm volatile("ldmatrix.sync.aligned.m8n8.x4.shared.b16 {%0,%1,%2,%3}, [%4];"
                 : "=r"(r[0]), "=r"(r[1]), "=r"(r[2]), "=r"(r[3]) : "r"(addr));
}
__device__ __forceinline__ void mma_bf16(float* c, const uint32_t* a,
                                         uint32_t b0, uint32_t b1) {
    asm volatile(
        "mma.sync.aligned.m16n8k16.row.col.f32.bf16.bf16.f32 "
        "{%0,%1,%2,%3}, {%4,%5,%6,%7}, {%8,%9}, {%0,%1,%2,%3};"
        : "+f"(c[0]), "+f"(c[1]), "+f"(c[2]), "+f"(c[3])
        : "r"(a[0]), "r"(a[1]), "r"(a[2]), "r"(a[3]), "r"(b0), "r"(b1));
}
#define SW128(x) ((x) ^ (((x) >> 3) & 0x70))

// ---------------- RoPE table ----------------
__global__ void rope_table_kernel(const int* __restrict__ tp) {
    int idx = blockIdx.x * blockDim.x + threadIdx.x;
    if (idx >= SEQ * (DK / 2)) return;
    int s = idx / (DK / 2), i = idx % (DK / 2);
    float invf = 1.0f / powf(10000.0f, (float)(2 * i) / (float)DK);
    double a = (double)((float)tp[s] * invf);
    g_cos[idx] = (float)cos(a);
    g_sin[idx] = (float)sin(a);
}

// ---------------- fp32 -> (hi,lo) bf16 split ----------------
__global__ void split_kernel(const float* __restrict__ in,
                             __nv_bfloat16* __restrict__ hi,
                             __nv_bfloat16* __restrict__ lo, int n) {
    int i = blockIdx.x * blockDim.x + threadIdx.x;
    if (i >= n) return;
    float v = in[i];
    __nv_bfloat16 h = __float2bfloat16(v);
    hi[i] = h;
    lo[i] = __float2bfloat16(v - __bfloat162float(h));
}

// ============ HMMA split-bf16 GEMM: C[M,N] = A[M,K] @ B[N,K]^T ============
// CTA 128x128, 8 warps as 4(m) x 2(n): warp tile 32x64 = 2 m16 x 8 n8.
// Stage (KC=64): Ah | Al | Bh | Bl, each 128 rows x 128B (SW128), 16KB -> 64KB.
template<bool ROPE>
__global__ __launch_bounds__(256, 1) void gemm_mma(
    const __nv_bfloat16* __restrict__ aHi, const __nv_bfloat16* __restrict__ aLo,
    const __nv_bfloat16* __restrict__ bHi, const __nv_bfloat16* __restrict__ bLo,
    float* __restrict__ C)
{
    extern __shared__ char smraw[];
    const uint32_t buf0 = smem_u32(smraw);

    const int tid  = threadIdx.x;
    const int w    = tid >> 5;
    const int lane = tid & 31;
    const int m0   = blockIdx.y * 128;
    const int n0   = blockIdx.x * 128;

    const __nv_bfloat16* srcs[4] = { aHi, aLo, bHi, bLo };

    // -------- stage loader: 4096 x 16B chunks, 16 per thread --------
    auto load_stage = [&](int s) {
        uint32_t sbase = buf0 + (uint32_t)(s & 1) * STAGE_B;
#pragma unroll
        for (int i = 0; i < 16; ++i) {
            int c   = tid + 256 * i;
            int sub = i >> 2;                  // c>>10 (exact since tid<256)
            int cc  = c & 1023;
            int r   = cc >> 3;
            int kc  = cc & 7;
            const __nv_bfloat16* src = srcs[sub] +
                (size_t)((sub < 2 ? m0 : n0) + r) * DMODEL + s * KC + kc * 8;
            uint32_t dst = sbase + (uint32_t)sub * 16384u +
                           SW128((uint32_t)(r * 128 + kc * 16));
            cpa16(dst, src);
        }
        cpa_commit();
    };

    float acc[2][8][4];
#pragma unroll
    for (int mt = 0; mt < 2; ++mt)
#pragma unroll
        for (int nt = 0; nt < 8; ++nt)
#pragma unroll
            for (int e = 0; e < 4; ++e) acc[mt][nt][e] = 0.f;

    const int lrow = lane & 15;
    const int lhalf = (lane >> 4) & 1;   // k-chunk select within 32B
    const uint32_t arowbase = (uint32_t)(((w & 3) * 32 + lrow) * 128);
    const uint32_t browbase = (uint32_t)(((w >> 2) * 64 + lrow) * 128);

    load_stage(0);

    for (int s = 0; s < NST; ++s) {
        if (s + 1 < NST) { load_stage(s + 1); cpa_wait1(); }
        else             { cpa_wait0(); }
        __syncthreads();

        const uint32_t sbase = buf0 + (uint32_t)(s & 1) * STAGE_B;
#pragma unroll
        for (int kq = 0; kq < 4; ++kq) {
            const uint32_t koff = (uint32_t)(kq * 32 + lhalf * 16);
            uint32_t ah[2][4], al[2][4], bh[4][4], bl[4][4];
#pragma unroll
            for (int mt = 0; mt < 2; ++mt) {
                uint32_t off = SW128(arowbase + (uint32_t)(mt * 16 * 128) + koff);
                ldsm4(ah[mt], sbase + off);
                ldsm4(al[mt], sbase + 16384u + off);
            }
#pragma unroll
            for (int bt = 0; bt < 4; ++bt) {
                uint32_t off = SW128(browbase + (uint32_t)(bt * 16 * 128) + koff);
                ldsm4(bh[bt], sbase + 32768u + off);
                ldsm4(bl[bt], sbase + 49152u + off);
            }
#pragma unroll
            for (int mt = 0; mt < 2; ++mt)
#pragma unroll
                for (int bt = 0; bt < 4; ++bt)
#pragma unroll
                    for (int hf = 0; hf < 2; ++hf) {
                        float* c = acc[mt][bt * 2 + hf];
                        mma_bf16(c, ah[mt], bh[bt][hf], bh[bt][hf + 2]);
                        mma_bf16(c, ah[mt], bl[bt][hf], bl[bt][hf + 2]);
                        mma_bf16(c, al[mt], bh[bt][hf], bh[bt][hf + 2]);
                    }
        }
        __syncthreads();
    }

    // -------- epilogue: c-frag rows m=lane>>2 (+8), cols n=2*(lane&3)+{0,1} ----
    const int trow  = lane >> 2;
    const int tcol2 = (lane & 3) * 2;
#pragma unroll
    for (int mt = 0; mt < 2; ++mt) {
#pragma unroll
        for (int nt = 0; nt < 8; ++nt) {
            const int n = n0 + (w >> 2) * 64 + (nt >> 1) * 16 + (nt & 1) * 8 + tcol2;
            float v[4] = { acc[mt][nt][0], acc[mt][nt][1],
                           acc[mt][nt][2], acc[mt][nt][3] };
            const int r0 = m0 + (w & 3) * 32 + mt * 16 + trow;
            if (ROPE) {
                const int pr = (n & (DK - 1)) >> 1;
                {
                    const int pos = r0 & (SEQ - 1);
                    float cs = g_cos[pos * (DK / 2) + pr];
                    float sn = g_sin[pos * (DK / 2) + pr];
                    float x1 = v[0], x2 = v[1];
                    v[0] = x1 * cs - x2 * sn; v[1] = x1 * sn + x2 * cs;
                }
                {
                    const int pos = (r0 + 8) & (SEQ - 1);
                    float cs = g_cos[pos * (DK / 2) + pr];
                    float sn = g_sin[pos * (DK / 2) + pr];
                    float x1 = v[2], x2 = v[3];
                    v[2] = x1 * cs - x2 * sn; v[3] = x1 * sn + x2 * cs;
                }
            }
            *(float2*)(C + (size_t)r0 * DMODEL + n)       = make_float2(v[0], v[1]);
            *(float2*)(C + (size_t)(r0 + 8) * DMODEL + n) = make_float2(v[2], v[3]);
        }
    }
}

// ---------------- causal flash attention, fp32 (unchanged, passing) ----------------
__global__ __launch_bounds__(256) void attn_kernel(
    const float* __restrict__ Q, const float* __restrict__ Kg,
    const float* __restrict__ Vg, float* __restrict__ Og)
{
    extern __shared__ __align__(16) float sm[];
    float* Qs = sm;
    float* Ks = Qs + 64 * 132;
    float* Vs = Ks + 64 * 132;
    float* Ps = Vs + 64 * 128;

    const int tid = threadIdx.x;
    const int tx = tid & 15, ty = tid >> 4;
    const int qb = blockIdx.x, bh = blockIdx.y;
    const int b = bh >> 4, h = bh & 15;
    const int q0 = qb * 64;
    const size_t base = (size_t)b * SEQ * DMODEL + (size_t)h * DK;

    for (int f = tid; f < 64 * 32; f += 256) {
        int r = f >> 5, c4 = (f & 31) << 2;
        *(float4*)(Qs + r * 132 + c4) =
            *(const float4*)(Q + base + (size_t)(q0 + r) * DMODEL + c4);
    }

    float m_i[4], l_i[4], O[4][8];
#pragma unroll
    for (int i = 0; i < 4; ++i) {
        m_i[i] = -1e30f; l_i[i] = 0.f;
#pragma unroll
        for (int jd = 0; jd < 8; ++jd) O[i][jd] = 0.f;
    }
    const float scale = 0.08838834764831845f;

    for (int kb = 0; kb <= qb; ++kb) {
        const int k0 = kb * 64;
        __syncthreads();
        for (int f = tid; f < 64 * 32; f += 256) {
            int r = f >> 5, c4 = (f & 31) << 2;
            *(float4*)(Ks + r * 132 + c4) =
                *(const float4*)(Kg + base + (size_t)(k0 + r) * DMODEL + c4);
            *(float4*)(Vs + r * 128 + c4) =
                *(const float4*)(Vg + base + (size_t)(k0 + r) * DMODEL + c4);
        }
        __syncthreads();

        float s[4][4];
#pragma unroll
        for (int i = 0; i < 4; ++i)
#pragma unroll
            for (int j = 0; j < 4; ++j) s[i][j] = 0.f;

#pragma unroll 8
        for (int d4 = 0; d4 < 32; ++d4) {
            float4 kvv[4], qvv[4];
#pragma unroll
            for (int j = 0; j < 4; ++j)
                kvv[j] = *(const float4*)(Ks + (tx + 16 * j) * 132 + 4 * d4);
#pragma unroll
            for (int i = 0; i < 4; ++i)
                qvv[i] = *(const float4*)(Qs + (ty * 4 + i) * 132 + 4 * d4);
#pragma unroll
            for (int i = 0; i < 4; ++i)
#pragma unroll
                for (int j = 0; j < 4; ++j)
                    s[i][j] += qvv[i].x * kvv[j].x + qvv[i].y * kvv[j].y +
                               qvv[i].z * kvv[j].z + qvv[i].w * kvv[j].w;
        }

        const bool diag = (kb == qb);
#pragma unroll
        for (int i = 0; i < 4; ++i) {
            const int qg = q0 + ty * 4 + i;
            float mx = -1e30f;
#pragma unroll
            for (int j = 0; j < 4; ++j) {
                float sv = s[i][j] * scale;
                if (diag && (k0 + tx + 16 * j > qg)) sv = -1e30f;
                s[i][j] = sv;
                mx = fmaxf(mx, sv);
            }
#pragma unroll
            for (int off = 8; off > 0; off >>= 1)
                mx = fmaxf(mx, __shfl_xor_sync(0xffffffffu, mx, off));
            float mnew = fmaxf(m_i[i], mx);
            float alpha = __expf(m_i[i] - mnew);
            float psum = 0.f;
#pragma unroll
            for (int j = 0; j < 4; ++j) {
                float p = __expf(s[i][j] - mnew);
                Ps[(ty * 4 + i) * 68 + tx + 16 * j] = p;
                psum += p;
            }
#pragma unroll
            for (int off = 8; off > 0; off >>= 1)
                psum += __shfl_xor_sync(0xffffffffu, psum, off);
            l_i[i] = l_i[i] * alpha + psum;
            m_i[i] = mnew;
#pragma unroll
            for (int jd = 0; jd < 8; ++jd) O[i][jd] *= alpha;
        }
        __syncthreads();

#pragma unroll 4
        for (int kk = 0; kk < 64; ++kk) {
            float pv[4];
#pragma unroll
            for (int i = 0; i < 4; ++i) pv[i] = Ps[(ty * 4 + i) * 68 + kk];
#pragma unroll
            for (int jd = 0; jd < 8; ++jd) {
                float vv = Vs[kk * 128 + tx + 16 * jd];
#pragma unroll
                for (int i = 0; i < 4; ++i) O[i][jd] += pv[i] * vv;
            }
        }
    }

#pragma unroll
    for (int i = 0; i < 4; ++i) {
        float inv = 1.0f / l_i[i];
        size_t rowb = ((size_t)b * SEQ + q0 + ty * 4 + i) * DMODEL + (size_t)h * DK;
#pragma unroll
        for (int jd = 0; jd < 8; ++jd)
            Og[rowb + tx + 16 * jd] = O[i][jd] * inv;
    }
}

// ---------------------------------------------------------------------------------
extern "C" void kernel_launch(void* const* d_in, const int* in_sizes, int n_in,
                              void* d_out, int out_size)
{
    const float* x  = (const float*)d_in[0];
    const int*   tp = (const int*)  d_in[1];
    const float* w[4] = { (const float*)d_in[2], (const float*)d_in[3],
                          (const float*)d_in[4], (const float*)d_in[5] };
    float* out = (float*)d_out;

    float *qp, *kp, *vp, *aop;
    __nv_bfloat16 *xh, *xl, *aoh, *aol, *wh, *wl;
    cudaGetSymbolAddress((void**)&qp,  g_q);
    cudaGetSymbolAddress((void**)&kp,  g_k);
    cudaGetSymbolAddress((void**)&vp,  g_v);
    cudaGetSymbolAddress((void**)&aop, g_ao);
    cudaGetSymbolAddress((void**)&xh,  g_xHi);
    cudaGetSymbolAddress((void**)&xl,  g_xLo);
    cudaGetSymbolAddress((void**)&aoh, g_aoHi);
    cudaGetSymbolAddress((void**)&aol, g_aoLo);
    cudaGetSymbolAddress((void**)&wh,  g_wHi);
    cudaGetSymbolAddress((void**)&wl,  g_wLo);

    rope_table_kernel<<<(SEQ * (DK / 2) + 255) / 256, 256>>>(tp);

    const int NX = MTOT * DMODEL, NW = DMODEL * DMODEL;
    split_kernel<<<(NX + 255) / 256, 256>>>(x, xh, xl, NX);
    for (int i = 0; i < 4; ++i)
        split_kernel<<<(NW + 255) / 256, 256>>>(w[i], wh + (size_t)i * NW,
                                                wl + (size_t)i * NW, NW);

    const int GSMEM = 2 * STAGE_B;  // 131072
    cudaFuncSetAttribute(gemm_mma<true >, cudaFuncAttributeMaxDynamicSharedMemorySize, GSMEM);
    cudaFuncSetAttribute(gemm_mma<false>, cudaFuncAttributeMaxDynamicSharedMemorySize, GSMEM);

    dim3 gg(DMODEL / 128, MTOT / 128);  // (16, 32)
    gemm_mma<true ><<<gg, 256, GSMEM>>>(xh, xl, wh + 0 * (size_t)NW, wl + 0 * (size_t)NW, qp);
    gemm_mma<true ><<<gg, 256, GSMEM>>>(xh, xl, wh + 1 * (size_t)NW, wl + 1 * (size_t)NW, kp);
    gemm_mma<false><<<gg, 256, GSMEM>>>(xh, xl, wh + 2 * (size_t)NW, wl + 2 * (size_t)NW, vp);

    const int ATTN_SMEM = (64 * 132 + 64 * 132 + 64 * 128 + 64 * 68) * 4;
    cudaFuncSetAttribute(attn_kernel, cudaFuncAttributeMaxDynamicSharedMemorySize, ATTN_SMEM);
    attn_kernel<<<dim3(SEQ / 64, BATCH * NHEADS), 256, ATTN_SMEM>>>(qp, kp, vp, aop);

    split_kernel<<<(NX + 255) / 256, 256>>>(aop, aoh, aol, NX);
    gemm_mma<false><<<gg, 256, GSMEM>>>(aoh, aol, wh + 3 * (size_t)NW, wl + 3 * (size_t)NW, out);
}

// round 5
// speedup vs baseline: 2.2955x; 1.4499x over previous
#include <cuda_runtime.h>
#include <cuda_bf16.h>
#include <math.h>
#include <stdint.h>

#define BATCH   2
#define SEQ     2048
#define DMODEL  2048
#define NHEADS  16
#define DK      128
#define MTOT    (BATCH * SEQ)
#define KC      64
#define NST     (DMODEL / KC)
#define STAGE_B 65536
#define BQ      128
#define BK      64

// ---------------- scratch ----------------
__device__ float g_v [(size_t)MTOT * DMODEL];
__device__ float g_cos[SEQ * (DK / 2)];
__device__ float g_sin[SEQ * (DK / 2)];
__device__ __nv_bfloat16 g_xHi [(size_t)MTOT * DMODEL];
__device__ __nv_bfloat16 g_xLo [(size_t)MTOT * DMODEL];
__device__ __nv_bfloat16 g_qHi [(size_t)MTOT * DMODEL];
__device__ __nv_bfloat16 g_qLo [(size_t)MTOT * DMODEL];
__device__ __nv_bfloat16 g_kHi [(size_t)MTOT * DMODEL];
__device__ __nv_bfloat16 g_kLo [(size_t)MTOT * DMODEL];
__device__ __nv_bfloat16 g_aoHi[(size_t)MTOT * DMODEL];
__device__ __nv_bfloat16 g_aoLo[(size_t)MTOT * DMODEL];
__device__ __nv_bfloat16 g_wHi [(size_t)4 * DMODEL * DMODEL];
__device__ __nv_bfloat16 g_wLo [(size_t)4 * DMODEL * DMODEL];

// ---------------- PTX helpers ----------------
__device__ __forceinline__ uint32_t smem_u32(const void* p) {
    uint32_t a;
    asm("{ .reg .u64 t; cvta.to.shared.u64 t, %1; cvt.u32.u64 %0, t; }" : "=r"(a) : "l"(p));
    return a;
}
__device__ __forceinline__ void cpa16(uint32_t dst, const void* src) {
    asm volatile("cp.async.cg.shared.global [%0], [%1], 16;" :: "r"(dst), "l"(src) : "memory");
}
__device__ __forceinline__ void cpa_commit() { asm volatile("cp.async.commit_group;" ::: "memory"); }
__device__ __forceinline__ void cpa_wait1()  { asm volatile("cp.async.wait_group 1;" ::: "memory"); }
__device__ __forceinline__ void cpa_wait0()  { asm volatile("cp.async.wait_group 0;" ::: "memory"); }
__device__ __forceinline__ void ldsm4(uint32_t* r, uint32_t addr) {
    asm volatile("ldmatrix.sync.aligned.m8n8.x4.shared.b16 {%0,%1,%2,%3}, [%4];"
                 : "=r"(r[0]), "=r"(r[1]), "=r"(r[2]), "=r"(r[3]) : "r"(addr));
}
__device__ __forceinline__ void mma_bf16(float* c, const uint32_t* a, uint32_t b0, uint32_t b1) {
    asm volatile(
        "mma.sync.aligned.m16n8k16.row.col.f32.bf16.bf16.f32 "
        "{%0,%1,%2,%3}, {%4,%5,%6,%7}, {%8,%9}, {%0,%1,%2,%3};"
        : "+f"(c[0]), "+f"(c[1]), "+f"(c[2]), "+f"(c[3])
        : "r"(a[0]), "r"(a[1]), "r"(a[2]), "r"(a[3]), "r"(b0), "r"(b1));
}
__device__ __forceinline__ void mma_tf32(float* c, const uint32_t* a, uint32_t b0, uint32_t b1) {
    asm volatile(
        "mma.sync.aligned.m16n8k8.row.col.f32.tf32.tf32.f32 "
        "{%0,%1,%2,%3}, {%4,%5,%6,%7}, {%8,%9}, {%0,%1,%2,%3};"
        : "+f"(c[0]), "+f"(c[1]), "+f"(c[2]), "+f"(c[3])
        : "r"(a[0]), "r"(a[1]), "r"(a[2]), "r"(a[3]), "r"(b0), "r"(b1));
}
__device__ __forceinline__ uint32_t f2tf32(float x) {
    uint32_t t;
    asm("cvt.rna.tf32.f32 %0, %1;" : "=r"(t) : "f"(x));
    return t;
}
__device__ __forceinline__ uint32_t lds32(uint32_t a) {
    uint32_t v;
    asm volatile("ld.shared.b32 %0, [%1];" : "=r"(v) : "r"(a));
    return v;
}
__device__ __forceinline__ void sts32(uint32_t a, uint32_t v) {
    asm volatile("st.shared.b32 [%0], %1;" :: "r"(a), "r"(v) : "memory");
}
__device__ __forceinline__ void sts128(uint32_t dst, uint4 v) {
    asm volatile("st.shared.v4.b32 [%0], {%1, %2, %3, %4};"
                 :: "r"(dst), "r"(v.x), "r"(v.y), "r"(v.z), "r"(v.w) : "memory");
}
#define SW128(x) ((x) ^ (((x) >> 3) & 0x70))

// ---------------- RoPE table ----------------
__global__ void rope_table_kernel(const int* __restrict__ tp) {
    int idx = blockIdx.x * blockDim.x + threadIdx.x;
    if (idx >= SEQ * (DK / 2)) return;
    int s = idx / (DK / 2), i = idx % (DK / 2);
    float invf = 1.0f / powf(10000.0f, (float)(2 * i) / (float)DK);
    double a = (double)((float)tp[s] * invf);
    g_cos[idx] = (float)cos(a);
    g_sin[idx] = (float)sin(a);
}

// ---------------- fp32 -> (hi,lo) bf16 split ----------------
__global__ void split_kernel(const float* __restrict__ in,
                             __nv_bfloat16* __restrict__ hi,
                             __nv_bfloat16* __restrict__ lo, int n) {
    int i = blockIdx.x * blockDim.x + threadIdx.x;
    if (i >= n) return;
    float v = in[i];
    __nv_bfloat16 h = __float2bfloat16(v);
    hi[i] = h;
    lo[i] = __float2bfloat16(v - __bfloat162float(h));
}

// ============ HMMA split-bf16 GEMM ============
template<bool ROPE, bool SPLIT>
__global__ __launch_bounds__(256, 1) void gemm_mma(
    const __nv_bfloat16* __restrict__ aHi, const __nv_bfloat16* __restrict__ aLo,
    const __nv_bfloat16* __restrict__ bHi, const __nv_bfloat16* __restrict__ bLo,
    float* __restrict__ C, __nv_bfloat16* __restrict__ Ch, __nv_bfloat16* __restrict__ Cl)
{
    extern __shared__ char smraw[];
    const uint32_t buf0 = smem_u32(smraw);
    const int tid = threadIdx.x, w = tid >> 5, lane = tid & 31;
    const int m0 = blockIdx.y * 128, n0 = blockIdx.x * 128;
    const __nv_bfloat16* srcs[4] = { aHi, aLo, bHi, bLo };

    auto load_stage = [&](int s) {
        uint32_t sbase = buf0 + (uint32_t)(s & 1) * STAGE_B;
#pragma unroll
        for (int i = 0; i < 16; ++i) {
            int c = tid + 256 * i;
            int sub = i >> 2;
            int cc = c & 1023, r = cc >> 3, kc = cc & 7;
            const __nv_bfloat16* src = srcs[sub] +
                (size_t)((sub < 2 ? m0 : n0) + r) * DMODEL + s * KC + kc * 8;
            cpa16(sbase + (uint32_t)sub * 16384u + SW128((uint32_t)(r * 128 + kc * 16)), src);
        }
        cpa_commit();
    };

    float acc[2][8][4];
#pragma unroll
    for (int mt = 0; mt < 2; ++mt)
#pragma unroll
        for (int nt = 0; nt < 8; ++nt)
#pragma unroll
            for (int e = 0; e < 4; ++e) acc[mt][nt][e] = 0.f;

    const int lrow = lane & 15, lhalf = (lane >> 4) & 1;
    const uint32_t arowbase = (uint32_t)(((w & 3) * 32 + lrow) * 128);
    const uint32_t browbase = (uint32_t)(((w >> 2) * 64 + lrow) * 128);

    load_stage(0);
    for (int s = 0; s < NST; ++s) {
        if (s + 1 < NST) { load_stage(s + 1); cpa_wait1(); }
        else             { cpa_wait0(); }
        __syncthreads();
        const uint32_t sbase = buf0 + (uint32_t)(s & 1) * STAGE_B;
#pragma unroll
        for (int kq = 0; kq < 4; ++kq) {
            const uint32_t koff = (uint32_t)(kq * 32 + lhalf * 16);
            uint32_t ah[2][4], al[2][4], bh[4][4], bl[4][4];
#pragma unroll
            for (int mt = 0; mt < 2; ++mt) {
                uint32_t off = SW128(arowbase + (uint32_t)(mt * 16 * 128) + koff);
                ldsm4(ah[mt], sbase + off);
                ldsm4(al[mt], sbase + 16384u + off);
            }
#pragma unroll
            for (int bt = 0; bt < 4; ++bt) {
                uint32_t off = SW128(browbase + (uint32_t)(bt * 16 * 128) + koff);
                ldsm4(bh[bt], sbase + 32768u + off);
                ldsm4(bl[bt], sbase + 49152u + off);
            }
#pragma unroll
            for (int mt = 0; mt < 2; ++mt)
#pragma unroll
                for (int bt = 0; bt < 4; ++bt)
#pragma unroll
                    for (int hf = 0; hf < 2; ++hf) {
                        float* c = acc[mt][bt * 2 + hf];
                        mma_bf16(c, ah[mt], bh[bt][hf], bh[bt][hf + 2]);
                        mma_bf16(c, ah[mt], bl[bt][hf], bl[bt][hf + 2]);
                        mma_bf16(c, al[mt], bh[bt][hf], bh[bt][hf + 2]);
                    }
        }
        __syncthreads();
    }

    const int trow = lane >> 2, tcol2 = (lane & 3) * 2;
#pragma unroll
    for (int mt = 0; mt < 2; ++mt) {
#pragma unroll
        for (int nt = 0; nt < 8; ++nt) {
            const int n = n0 + (w >> 2) * 64 + (nt >> 1) * 16 + (nt & 1) * 8 + tcol2;
            float v[4] = { acc[mt][nt][0], acc[mt][nt][1], acc[mt][nt][2], acc[mt][nt][3] };
            const int r0 = m0 + (w & 3) * 32 + mt * 16 + trow;
            if (ROPE) {
                const int pr = (n & (DK - 1)) >> 1;
                {
                    const int pos = r0 & (SEQ - 1);
                    float cs = g_cos[pos * (DK / 2) + pr], sn = g_sin[pos * (DK / 2) + pr];
                    float x1 = v[0], x2 = v[1];
                    v[0] = x1 * cs - x2 * sn; v[1] = x1 * sn + x2 * cs;
                }
                {
                    const int pos = (r0 + 8) & (SEQ - 1);
                    float cs = g_cos[pos * (DK / 2) + pr], sn = g_sin[pos * (DK / 2) + pr];
                    float x1 = v[2], x2 = v[3];
                    v[2] = x1 * cs - x2 * sn; v[3] = x1 * sn + x2 * cs;
                }
            }
            if (SPLIT) {
#pragma unroll
                for (int half = 0; half < 2; ++half) {
                    float a0 = v[half * 2], a1 = v[half * 2 + 1];
                    __nv_bfloat16 h0 = __float2bfloat16(a0);
                    __nv_bfloat16 h1 = __float2bfloat16(a1);
                    __nv_bfloat16 l0 = __float2bfloat16(a0 - __bfloat162float(h0));
                    __nv_bfloat16 l1 = __float2bfloat16(a1 - __bfloat162float(h1));
                    size_t off = (size_t)(r0 + half * 8) * DMODEL + n;
                    *(__nv_bfloat162*)(Ch + off) = __nv_bfloat162(h0, h1);
                    *(__nv_bfloat162*)(Cl + off) = __nv_bfloat162(l0, l1);
                }
            } else {
                *(float2*)(C + (size_t)r0 * DMODEL + n)       = make_float2(v[0], v[1]);
                *(float2*)(C + (size_t)(r0 + 8) * DMODEL + n) = make_float2(v[2], v[3]);
            }
        }
    }
}

// ============ tensor-core causal flash attention ============
// Bq=128 (CTA), Bk=64, Dk=128. 8 warps: wm=w>>1 (4), wn=w&1 (2).
// QK: split-bf16 HMMA (warp 32x32).  PV: tf32 m16n8k8 (warp 32x64), P,V single tf32 rna.
#define A_QH  0u
#define A_QL  32768u
#define A_KH  65536u
#define A_KL  81920u
#define A_V   98304u       /* 64 x 132 fp32 = 33792 */
#define A_P   132096u      /* 128 x 68 fp32 = 34816 */
#define A_RM  166912u      /* 2 x 128 fp32  */
#define A_RS  167936u      /* 2 x 128 fp32  */
#define ATTN_SM 168960

__global__ __launch_bounds__(256, 1) void attn_mma(
    const __nv_bfloat16* __restrict__ qh, const __nv_bfloat16* __restrict__ ql,
    const __nv_bfloat16* __restrict__ kh, const __nv_bfloat16* __restrict__ kl,
    const float* __restrict__ vf,
    __nv_bfloat16* __restrict__ aoh, __nv_bfloat16* __restrict__ aol)
{
    extern __shared__ char smraw[];
    const uint32_t S0 = smem_u32(smraw);
    const int tid = threadIdx.x, w = tid >> 5, lane = tid & 31;
    const int wm = w >> 1, wn = w & 1;
    const int lrow = lane & 15, lhalf = lane >> 4;
    const int qb = blockIdx.x, bh = blockIdx.y, b = bh >> 4, h = bh & 15;
    const int q0 = qb * BQ;
    const size_t rowbase = (size_t)b * SEQ;
    const int hoff = h * DK;
    const float scale = 0.08838834764831845f;

    // persistent Q tile (hi/lo), 2 panels of 16KB each
#pragma unroll
    for (int i = 0; i < 8; ++i) {
        int c = tid + 256 * i;           // 0..2047
        int r = c >> 4, kc = c & 15;
        uint32_t off = ((uint32_t)(kc >> 3)) * 16384u + SW128((uint32_t)(r * 128 + (kc & 7) * 16));
        const size_t gsrc = (rowbase + q0 + r) * DMODEL + hoff + kc * 8;
        cpa16(S0 + A_QH + off, qh + gsrc);
        cpa16(S0 + A_QL + off, ql + gsrc);
    }
    cpa_commit();

    float m_i[4], l_i[4], oacc[2][8][4];
#pragma unroll
    for (int ri = 0; ri < 4; ++ri) { m_i[ri] = -1e30f; l_i[ri] = 0.f; }
#pragma unroll
    for (int mt = 0; mt < 2; ++mt)
#pragma unroll
        for (int c8 = 0; c8 < 8; ++c8)
#pragma unroll
            for (int e = 0; e < 4; ++e) oacc[mt][c8][e] = 0.f;

    const int ktiles = 2 * qb + 2;
    for (int kt = 0; kt < ktiles; ++kt) {
        const int k0 = kt * BK;
        __syncthreads();   // previous PV / P use complete

        // K tile hi/lo via cp.async (2 panels of 8KB)
#pragma unroll
        for (int i = 0; i < 4; ++i) {
            int c = tid + 256 * i;       // 0..1023
            int r = c >> 4, kc = c & 15;
            uint32_t off = ((uint32_t)(kc >> 3)) * 8192u + SW128((uint32_t)(r * 128 + (kc & 7) * 16));
            const size_t gsrc = (rowbase + k0 + r) * DMODEL + hoff + kc * 8;
            cpa16(S0 + A_KH + off, kh + gsrc);
            cpa16(S0 + A_KL + off, kl + gsrc);
        }
        cpa_commit();
        // V tile via LDG + rna(tf32) + STS, [64][132] fp32
#pragma unroll
        for (int i = 0; i < 8; ++i) {
            int c = tid + 256 * i;       // 0..2047
            int r = c >> 5, cc = c & 31;
            float4 v4 = *(const float4*)(vf + (rowbase + k0 + r) * DMODEL + hoff + cc * 4);
            uint4 t = make_uint4(f2tf32(v4.x), f2tf32(v4.y), f2tf32(v4.z), f2tf32(v4.w));
            sts128(S0 + A_V + (uint32_t)(r * 528 + cc * 16), t);
        }
        cpa_wait0();
        __syncthreads();

        // ---- S = Q K^T (split bf16, 3 terms) ----
        float sacc[2][4][4];
#pragma unroll
        for (int mt = 0; mt < 2; ++mt)
#pragma unroll
            for (int c = 0; c < 4; ++c)
#pragma unroll
                for (int e = 0; e < 4; ++e) sacc[mt][c][e] = 0.f;

#pragma unroll
        for (int kq = 0; kq < 8; ++kq) {
            const uint32_t koff = (uint32_t)((kq & 3) * 32 + lhalf * 16);
            const uint32_t pq = ((uint32_t)(kq >> 2)) * 16384u;
            const uint32_t pk = ((uint32_t)(kq >> 2)) * 8192u;
            uint32_t ah[2][4], al[2][4], bh_[2][4], bl_[2][4];
#pragma unroll
            for (int mt = 0; mt < 2; ++mt) {
                uint32_t off = pq + SW128((uint32_t)((wm * 32 + mt * 16 + lrow) * 128) + koff);
                ldsm4(ah[mt], S0 + A_QH + off);
                ldsm4(al[mt], S0 + A_QL + off);
            }
#pragma unroll
            for (int nt = 0; nt < 2; ++nt) {
                uint32_t off = pk + SW128((uint32_t)((wn * 32 + nt * 16 + lrow) * 128) + koff);
                ldsm4(bh_[nt], S0 + A_KH + off);
                ldsm4(bl_[nt], S0 + A_KL + off);
            }
#pragma unroll
            for (int mt = 0; mt < 2; ++mt)
#pragma unroll
                for (int nt = 0; nt < 2; ++nt)
#pragma unroll
                    for (int hf = 0; hf < 2; ++hf) {
                        float* c = sacc[mt][nt * 2 + hf];
                        mma_bf16(c, ah[mt], bh_[nt][hf], bh_[nt][hf + 2]);
                        mma_bf16(c, ah[mt], bl_[nt][hf], bl_[nt][hf + 2]);
                        mma_bf16(c, al[mt], bh_[nt][hf], bh_[nt][hf + 2]);
                    }
        }

        // ---- softmax ----
        const bool needmask = (kt >= 2 * qb);
        float tmax[4] = { -1e30f, -1e30f, -1e30f, -1e30f };
#pragma unroll
        for (int mt = 0; mt < 2; ++mt)
#pragma unroll
            for (int c = 0; c < 4; ++c)
#pragma unroll
                for (int e = 0; e < 4; ++e) {
                    float sv = sacc[mt][c][e] * scale;
                    if (needmask) {
                        int qg = q0 + wm * 32 + mt * 16 + (lane >> 2) + ((e >> 1) << 3);
                        int kg = k0 + wn * 32 + c * 8 + ((lane & 3) << 1) + (e & 1);
                        if (kg > qg) sv = -1e30f;
                    }
                    sacc[mt][c][e] = sv;
                    int ri = mt * 2 + (e >> 1);
                    tmax[ri] = fmaxf(tmax[ri], sv);
                }
#pragma unroll
        for (int ri = 0; ri < 4; ++ri) {
            tmax[ri] = fmaxf(tmax[ri], __shfl_xor_sync(0xffffffffu, tmax[ri], 1));
            tmax[ri] = fmaxf(tmax[ri], __shfl_xor_sync(0xffffffffu, tmax[ri], 2));
        }
        if ((lane & 3) == 0) {
#pragma unroll
            for (int ri = 0; ri < 4; ++ri) {
                int rowl = wm * 32 + (ri >> 1) * 16 + (lane >> 2) + ((ri & 1) << 3);
                sts32(S0 + A_RM + (uint32_t)((wn * 128 + rowl) * 4), __float_as_uint(tmax[ri]));
            }
        }
        __syncthreads();

        float mnew[4], alpha[4];
#pragma unroll
        for (int ri = 0; ri < 4; ++ri) {
            int rowl = wm * 32 + (ri >> 1) * 16 + (lane >> 2) + ((ri & 1) << 3);
            float t0 = __uint_as_float(lds32(S0 + A_RM + (uint32_t)(rowl * 4)));
            float t1 = __uint_as_float(lds32(S0 + A_RM + (uint32_t)((128 + rowl) * 4)));
            mnew[ri] = fmaxf(m_i[ri], fmaxf(t0, t1));
            alpha[ri] = __expf(m_i[ri] - mnew[ri]);
            m_i[ri] = mnew[ri];
        }
#pragma unroll
        for (int mt = 0; mt < 2; ++mt)
#pragma unroll
            for (int c8 = 0; c8 < 8; ++c8)
#pragma unroll
                for (int e = 0; e < 4; ++e)
                    oacc[mt][c8][e] *= alpha[mt * 2 + (e >> 1)];

        float tsum[4] = { 0.f, 0.f, 0.f, 0.f };
#pragma unroll
        for (int mt = 0; mt < 2; ++mt)
#pragma unroll
            for (int c = 0; c < 4; ++c)
#pragma unroll
                for (int e = 0; e < 4; ++e) {
                    int ri = mt * 2 + (e >> 1);
                    float p = __expf(sacc[mt][c][e] - mnew[ri]);
                    tsum[ri] += p;
                    int rowl = wm * 32 + mt * 16 + (lane >> 2) + ((e >> 1) << 3);
                    int col  = wn * 32 + c * 8 + ((lane & 3) << 1) + (e & 1);
                    sts32(S0 + A_P + (uint32_t)((rowl * 68 + col) * 4), f2tf32(p));
                }
#pragma unroll
        for (int ri = 0; ri < 4; ++ri) {
            tsum[ri] += __shfl_xor_sync(0xffffffffu, tsum[ri], 1);
            tsum[ri] += __shfl_xor_sync(0xffffffffu, tsum[ri], 2);
        }
        if ((lane & 3) == 0) {
#pragma unroll
            for (int ri = 0; ri < 4; ++ri) {
                int rowl = wm * 32 + (ri >> 1) * 16 + (lane >> 2) + ((ri & 1) << 3);
                sts32(S0 + A_RS + (uint32_t)((wn * 128 + rowl) * 4), __float_as_uint(tsum[ri]));
            }
        }
        __syncthreads();
#pragma unroll
        for (int ri = 0; ri < 4; ++ri) {
            int rowl = wm * 32 + (ri >> 1) * 16 + (lane >> 2) + ((ri & 1) << 3);
            float s0 = __uint_as_float(lds32(S0 + A_RS + (uint32_t)(rowl * 4)));
            float s1 = __uint_as_float(lds32(S0 + A_RS + (uint32_t)((128 + rowl) * 4)));
            l_i[ri] = l_i[ri] * alpha[ri] + s0 + s1;
        }

        // ---- O += P V  (tf32 m16n8k8) ----
#pragma unroll
        for (int ks = 0; ks < 8; ++ks) {
            uint32_t a[2][4];
#pragma unroll
            for (int mt = 0; mt < 2; ++mt) {
                uint32_t r0a = S0 + A_P +
                    (uint32_t)(((wm * 32 + mt * 16 + (lane >> 2)) * 68 + ks * 8 + (lane & 3)) * 4);
                a[mt][0] = lds32(r0a);
                a[mt][1] = lds32(r0a + 8u * 68u * 4u);
                a[mt][2] = lds32(r0a + 16u);
                a[mt][3] = lds32(r0a + 8u * 68u * 4u + 16u);
            }
#pragma unroll
            for (int c8 = 0; c8 < 8; ++c8) {
                uint32_t baddr = S0 + A_V +
                    (uint32_t)(((ks * 8 + (lane & 3)) * 132 + wn * 64 + c8 * 8 + (lane >> 2)) * 4);
                uint32_t b0 = lds32(baddr);
                uint32_t b1 = lds32(baddr + 4u * 132u * 4u);
#pragma unroll
                for (int mt = 0; mt < 2; ++mt)
                    mma_tf32(oacc[mt][c8], a[mt], b0, b1);
            }
        }
    }

    // ---- epilogue: normalize + split bf16 out ----
#pragma unroll
    for (int mt = 0; mt < 2; ++mt)
#pragma unroll
        for (int c8 = 0; c8 < 8; ++c8)
#pragma unroll
            for (int hf = 0; hf < 2; ++hf) {
                int ri = mt * 2 + hf;
                float inv = 1.0f / l_i[ri];
                float a0 = oacc[mt][c8][hf * 2]     * inv;
                float a1 = oacc[mt][c8][hf * 2 + 1] * inv;
                int row = q0 + wm * 32 + mt * 16 + (lane >> 2) + hf * 8;
                int col = hoff + wn * 64 + c8 * 8 + ((lane & 3) << 1);
                __nv_bfloat16 h0 = __float2bfloat16(a0);
                __nv_bfloat16 h1 = __float2bfloat16(a1);
                __nv_bfloat16 l0 = __float2bfloat16(a0 - __bfloat162float(h0));
                __nv_bfloat16 l1 = __float2bfloat16(a1 - __bfloat162float(h1));
                size_t off = (rowbase + row) * DMODEL + col;
                *(__nv_bfloat162*)(aoh + off) = __nv_bfloat162(h0, h1);
                *(__nv_bfloat162*)(aol + off) = __nv_bfloat162(l0, l1);
            }
}

// ---------------------------------------------------------------------------------
extern "C" void kernel_launch(void* const* d_in, const int* in_sizes, int n_in,
                              void* d_out, int out_size)
{
    const float* x  = (const float*)d_in[0];
    const int*   tp = (const int*)  d_in[1];
    const float* w[4] = { (const float*)d_in[2], (const float*)d_in[3],
                          (const float*)d_in[4], (const float*)d_in[5] };
    float* out = (float*)d_out;

    float* vp;
    __nv_bfloat16 *xh, *xl, *qhh, *qll, *khh, *kll, *aoh, *aol, *wh, *wl;
    cudaGetSymbolAddress((void**)&vp,  g_v);
    cudaGetSymbolAddress((void**)&xh,  g_xHi);
    cudaGetSymbolAddress((void**)&xl,  g_xLo);
    cudaGetSymbolAddress((void**)&qhh, g_qHi);
    cudaGetSymbolAddress((void**)&qll, g_qLo);
    cudaGetSymbolAddress((void**)&khh, g_kHi);
    cudaGetSymbolAddress((void**)&kll, g_kLo);
    cudaGetSymbolAddress((void**)&aoh, g_aoHi);
    cudaGetSymbolAddress((void**)&aol, g_aoLo);
    cudaGetSymbolAddress((void**)&wh,  g_wHi);
    cudaGetSymbolAddress((void**)&wl,  g_wLo);

    rope_table_kernel<<<(SEQ * (DK / 2) + 255) / 256, 256>>>(tp);

    const int NX = MTOT * DMODEL, NW = DMODEL * DMODEL;
    split_kernel<<<(NX + 255) / 256, 256>>>(x, xh, xl, NX);
    for (int i = 0; i < 4; ++i)
        split_kernel<<<(NW + 255) / 256, 256>>>(w[i], wh + (size_t)i * NW,
                                                wl + (size_t)i * NW, NW);

    const int GSMEM = 2 * STAGE_B;
    cudaFuncSetAttribute(gemm_mma<true,  true >, cudaFuncAttributeMaxDynamicSharedMemorySize, GSMEM);
    cudaFuncSetAttribute(gemm_mma<false, false>, cudaFuncAttributeMaxDynamicSharedMemorySize, GSMEM);
    cudaFuncSetAttribute(attn_mma, cudaFuncAttributeMaxDynamicSharedMemorySize, ATTN_SM);

    dim3 gg(DMODEL / 128, MTOT / 128);
    gemm_mma<true,  true ><<<gg, 256, GSMEM>>>(xh, xl, wh + 0 * (size_t)NW, wl + 0 * (size_t)NW,
                                               nullptr, qhh, qll);
    gemm_mma<true,  true ><<<gg, 256, GSMEM>>>(xh, xl, wh + 1 * (size_t)NW, wl + 1 * (size_t)NW,
                                               nullptr, khh, kll);
    gemm_mma<false, false><<<gg, 256, GSMEM>>>(xh, xl, wh + 2 * (size_t)NW, wl + 2 * (size_t)NW,
                                               vp, nullptr, nullptr);

    attn_mma<<<dim3(SEQ / BQ, BATCH * NHEADS), 256, ATTN_SM>>>(qhh, qll, khh, kll, vp, aoh, aol);

    gemm_mma<false, false><<<gg, 256, GSMEM>>>(aoh, aol, wh + 3 * (size_t)NW, wl + 3 * (size_t)NW,
                                               out, nullptr, nullptr);
}

// round 6
// speedup vs baseline: 2.3076x; 1.0053x over previous
#include <cuda_runtime.h>
#include <cuda_bf16.h>
#include <math.h>
#include <stdint.h>

#define BATCH   2
#define SEQ     2048
#define DMODEL  2048
#define NHEADS  16
#define DK      128
#define MTOT    (BATCH * SEQ)
#define KC      64
#define NST     (DMODEL / KC)
#define STAGE_B 98304
#define GSMEM   (2 * STAGE_B)
#define BQ      128
#define BK      64

// ---------------- scratch ----------------
__device__ float g_v [(size_t)MTOT * DMODEL];
__device__ float g_cos[SEQ * (DK / 2)];
__device__ float g_sin[SEQ * (DK / 2)];
__device__ __nv_bfloat16 g_xHi [(size_t)MTOT * DMODEL];
__device__ __nv_bfloat16 g_xLo [(size_t)MTOT * DMODEL];
__device__ __nv_bfloat16 g_qHi [(size_t)MTOT * DMODEL];
__device__ __nv_bfloat16 g_qLo [(size_t)MTOT * DMODEL];
__device__ __nv_bfloat16 g_kHi [(size_t)MTOT * DMODEL];
__device__ __nv_bfloat16 g_kLo [(size_t)MTOT * DMODEL];
__device__ __nv_bfloat16 g_aoHi[(size_t)MTOT * DMODEL];
__device__ __nv_bfloat16 g_aoLo[(size_t)MTOT * DMODEL];
__device__ __nv_bfloat16 g_wHi [(size_t)4 * DMODEL * DMODEL];
__device__ __nv_bfloat16 g_wLo [(size_t)4 * DMODEL * DMODEL];

// ---------------- PTX helpers ----------------
__device__ __forceinline__ uint32_t smem_u32(const void* p) {
    uint32_t a;
    asm("{ .reg .u64 t; cvta.to.shared.u64 t, %1; cvt.u32.u64 %0, t; }" : "=r"(a) : "l"(p));
    return a;
}
__device__ __forceinline__ void cpa16(uint32_t dst, const void* src) {
    asm volatile("cp.async.cg.shared.global [%0], [%1], 16;" :: "r"(dst), "l"(src) : "memory");
}
__device__ __forceinline__ void cpa_commit() { asm volatile("cp.async.commit_group;" ::: "memory"); }
__device__ __forceinline__ void cpa_wait1()  { asm volatile("cp.async.wait_group 1;" ::: "memory"); }
__device__ __forceinline__ void cpa_wait0()  { asm volatile("cp.async.wait_group 0;" ::: "memory"); }
__device__ __forceinline__ void ldsm4(uint32_t* r, uint32_t addr) {
    asm volatile("ldmatrix.sync.aligned.m8n8.x4.shared.b16 {%0,%1,%2,%3}, [%4];"
                 : "=r"(r[0]), "=r"(r[1]), "=r"(r[2]), "=r"(r[3]) : "r"(addr));
}
__device__ __forceinline__ void mma_bf16(float* c, const uint32_t* a, uint32_t b0, uint32_t b1) {
    asm volatile(
        "mma.sync.aligned.m16n8k16.row.col.f32.bf16.bf16.f32 "
        "{%0,%1,%2,%3}, {%4,%5,%6,%7}, {%8,%9}, {%0,%1,%2,%3};"
        : "+f"(c[0]), "+f"(c[1]), "+f"(c[2]), "+f"(c[3])
        : "r"(a[0]), "r"(a[1]), "r"(a[2]), "r"(a[3]), "r"(b0), "r"(b1));
}
__device__ __forceinline__ void mma_tf32(float* c, const uint32_t* a, uint32_t b0, uint32_t b1) {
    asm volatile(
        "mma.sync.aligned.m16n8k8.row.col.f32.tf32.tf32.f32 "
        "{%0,%1,%2,%3}, {%4,%5,%6,%7}, {%8,%9}, {%0,%1,%2,%3};"
        : "+f"(c[0]), "+f"(c[1]), "+f"(c[2]), "+f"(c[3])
        : "r"(a[0]), "r"(a[1]), "r"(a[2]), "r"(a[3]), "r"(b0), "r"(b1));
}
__device__ __forceinline__ uint32_t f2tf32(float x) {
    uint32_t t;
    asm("cvt.rna.tf32.f32 %0, %1;" : "=r"(t) : "f"(x));
    return t;
}
__device__ __forceinline__ uint32_t lds32(uint32_t a) {
    uint32_t v;
    asm volatile("ld.shared.b32 %0, [%1];" : "=r"(v) : "r"(a));
    return v;
}
__device__ __forceinline__ void sts32(uint32_t a, uint32_t v) {
    asm volatile("st.shared.b32 [%0], %1;" :: "r"(a), "r"(v) : "memory");
}
__device__ __forceinline__ void sts128(uint32_t dst, uint4 v) {
    asm volatile("st.shared.v4.b32 [%0], {%1, %2, %3, %4};"
                 :: "r"(dst), "r"(v.x), "r"(v.y), "r"(v.z), "r"(v.w) : "memory");
}
#define SW128(x) ((x) ^ (((x) >> 3) & 0x70))

// ---------------- RoPE table ----------------
__global__ void rope_table_kernel(const int* __restrict__ tp) {
    int idx = blockIdx.x * blockDim.x + threadIdx.x;
    if (idx >= SEQ * (DK / 2)) return;
    int s = idx / (DK / 2), i = idx % (DK / 2);
    float invf = 1.0f / powf(10000.0f, (float)(2 * i) / (float)DK);
    double a = (double)((float)tp[s] * invf);
    g_cos[idx] = (float)cos(a);
    g_sin[idx] = (float)sin(a);
}

// ---------------- fp32 -> (hi,lo) bf16 splits ----------------
__global__ void split_kernel(const float* __restrict__ in,
                             __nv_bfloat16* __restrict__ hi,
                             __nv_bfloat16* __restrict__ lo, int n) {
    int i = blockIdx.x * blockDim.x + threadIdx.x;
    if (i >= n) return;
    float v = in[i];
    __nv_bfloat16 h = __float2bfloat16(v);
    hi[i] = h;
    lo[i] = __float2bfloat16(v - __bfloat162float(h));
}
__global__ void wsplit4_kernel(const float* __restrict__ w0, const float* __restrict__ w1,
                               const float* __restrict__ w2, const float* __restrict__ w3,
                               __nv_bfloat16* __restrict__ hi, __nv_bfloat16* __restrict__ lo) {
    const int NW = DMODEL * DMODEL;
    int i = blockIdx.x * blockDim.x + threadIdx.x;
    if (i >= NW) return;
    const float* w = (blockIdx.y == 0) ? w0 : (blockIdx.y == 1) ? w1 :
                     (blockIdx.y == 2) ? w2 : w3;
    size_t off = (size_t)blockIdx.y * NW + i;
    float v = w[i];
    __nv_bfloat16 h = __float2bfloat16(v);
    hi[off] = h;
    lo[off] = __float2bfloat16(v - __bfloat162float(h));
}

// ============ HMMA split-bf16 GEMM, CTA tile 128x256 ============
// MODE 0: fused QKV (N=6144 over concatenated weights); RoPE+split out for q/k, fp32 for v.
// MODE 1: Wo (N=2048), fp32 out.
// 8 warps: wm = w&3 (4 x 32 rows), wn2 = w>>2 (2 x 128 cols).
// Stage: Ah 16K | Al 16K | Bh 32K | Bl 32K = 96KB, double buffered.
template<int MODE>
__global__ __launch_bounds__(256, 1) void gemm2(
    const __nv_bfloat16* __restrict__ aHi, const __nv_bfloat16* __restrict__ aLo,
    const __nv_bfloat16* __restrict__ bHi, const __nv_bfloat16* __restrict__ bLo,
    float* __restrict__ vout,
    __nv_bfloat16* __restrict__ qh, __nv_bfloat16* __restrict__ ql,
    __nv_bfloat16* __restrict__ kh, __nv_bfloat16* __restrict__ kl,
    float* __restrict__ fout)
{
    extern __shared__ char smraw[];
    const uint32_t buf0 = smem_u32(smraw);
    const int tid = threadIdx.x, w = tid >> 5, lane = tid & 31;
    const int wm = w & 3, wn2 = w >> 2;
    const int m0 = blockIdx.y * 128, n0 = blockIdx.x * 256;

    auto load_stage = [&](int s) {
        uint32_t sbase = buf0 + (uint32_t)(s & 1) * STAGE_B;
#pragma unroll
        for (int i = 0; i < 24; ++i) {
            int c = tid + 256 * i;          // 0..6143
            const __nv_bfloat16* src;
            uint32_t dst;
            if (c < 2048) {                 // A: 2 panels of 1024 chunks
                int panel = c >> 10, cc = c & 1023, r = cc >> 3, kc = cc & 7;
                src = (panel ? aLo : aHi) + (size_t)(m0 + r) * DMODEL + s * KC + kc * 8;
                dst = sbase + (uint32_t)panel * 16384u + SW128((uint32_t)(r * 128 + kc * 16));
            } else {                        // B: 2 panels of 2048 chunks
                int c2 = c - 2048, panel = c2 >> 11, cc = c2 & 2047, r = cc >> 3, kc = cc & 7;
                src = (panel ? bLo : bHi) + (size_t)(n0 + r) * DMODEL + s * KC + kc * 8;
                dst = sbase + 32768u + (uint32_t)panel * 32768u +
                      SW128((uint32_t)(r * 128 + kc * 16));
            }
            cpa16(dst, src);
        }
        cpa_commit();
    };

    float acc[2][16][4];
#pragma unroll
    for (int mt = 0; mt < 2; ++mt)
#pragma unroll
        for (int nt = 0; nt < 16; ++nt)
#pragma unroll
            for (int e = 0; e < 4; ++e) acc[mt][nt][e] = 0.f;

    const int lrow = lane & 15, lhalf = (lane >> 4) & 1;

    load_stage(0);
    for (int s = 0; s < NST; ++s) {
        if (s + 1 < NST) { load_stage(s + 1); cpa_wait1(); }
        else             { cpa_wait0(); }
        __syncthreads();
        const uint32_t sbase = buf0 + (uint32_t)(s & 1) * STAGE_B;
#pragma unroll
        for (int kq = 0; kq < 4; ++kq) {
            const uint32_t koff = (uint32_t)(kq * 32 + lhalf * 16);
            uint32_t ah[2][4], al[2][4];
#pragma unroll
            for (int mt = 0; mt < 2; ++mt) {
                uint32_t off = SW128((uint32_t)((wm * 32 + mt * 16 + lrow) * 128) + koff);
                ldsm4(ah[mt], sbase + off);
                ldsm4(al[mt], sbase + 16384u + off);
            }
#pragma unroll
            for (int bt = 0; bt < 8; ++bt) {
                uint32_t off = SW128((uint32_t)((wn2 * 128 + bt * 16 + lrow) * 128) + koff);
                uint32_t bhv[4], blv[4];
                ldsm4(bhv, sbase + 32768u + off);
                ldsm4(blv, sbase + 65536u + off);
#pragma unroll
                for (int mt = 0; mt < 2; ++mt)
#pragma unroll
                    for (int hf = 0; hf < 2; ++hf) {
                        float* c = acc[mt][bt * 2 + hf];
                        mma_bf16(c, ah[mt], bhv[hf], bhv[hf + 2]);
                        mma_bf16(c, ah[mt], blv[hf], blv[hf + 2]);
                        mma_bf16(c, al[mt], bhv[hf], bhv[hf + 2]);
                    }
            }
        }
        __syncthreads();
    }

    const int trow = lane >> 2, tcol2 = (lane & 3) * 2;
    const int which = (MODE == 0) ? (n0 >> 11) : 3;   // uniform per CTA
#pragma unroll
    for (int mt = 0; mt < 2; ++mt) {
#pragma unroll
        for (int nt = 0; nt < 16; ++nt) {
            const int ng = n0 + wn2 * 128 + (nt >> 1) * 16 + (nt & 1) * 8 + tcol2;
            const int r0 = m0 + wm * 32 + mt * 16 + trow;
            float v[4] = { acc[mt][nt][0], acc[mt][nt][1], acc[mt][nt][2], acc[mt][nt][3] };
            if (MODE == 0 && which < 2) {
                const int ncol = ng & (DMODEL - 1);
                const int pr = (ncol & (DK - 1)) >> 1;
                {
                    const int pos = r0 & (SEQ - 1);
                    float cs = g_cos[pos * (DK / 2) + pr], sn = g_sin[pos * (DK / 2) + pr];
                    float x1 = v[0], x2 = v[1];
                    v[0] = x1 * cs - x2 * sn; v[1] = x1 * sn + x2 * cs;
                }
                {
                    const int pos = (r0 + 8) & (SEQ - 1);
                    float cs = g_cos[pos * (DK / 2) + pr], sn = g_sin[pos * (DK / 2) + pr];
                    float x1 = v[2], x2 = v[3];
                    v[2] = x1 * cs - x2 * sn; v[3] = x1 * sn + x2 * cs;
                }
            }
            if (MODE == 0) {
                const int ncol = ng & (DMODEL - 1);
                if (which < 2) {
                    __nv_bfloat16* H = which ? kh : qh;
                    __nv_bfloat16* L = which ? kl : ql;
#pragma unroll
                    for (int half = 0; half < 2; ++half) {
                        float a0 = v[half * 2], a1 = v[half * 2 + 1];
                        __nv_bfloat16 h0 = __float2bfloat16(a0);
                        __nv_bfloat16 h1 = __float2bfloat16(a1);
                        __nv_bfloat16 l0 = __float2bfloat16(a0 - __bfloat162float(h0));
                        __nv_bfloat16 l1 = __float2bfloat16(a1 - __bfloat162float(h1));
                        size_t off = (size_t)(r0 + half * 8) * DMODEL + ncol;
                        *(__nv_bfloat162*)(H + off) = __nv_bfloat162(h0, h1);
                        *(__nv_bfloat162*)(L + off) = __nv_bfloat162(l0, l1);
                    }
                } else {
                    *(float2*)(vout + (size_t)r0 * DMODEL + ncol)       = make_float2(v[0], v[1]);
                    *(float2*)(vout + (size_t)(r0 + 8) * DMODEL + ncol) = make_float2(v[2], v[3]);
                }
            } else {
                *(float2*)(fout + (size_t)r0 * DMODEL + ng)       = make_float2(v[0], v[1]);
                *(float2*)(fout + (size_t)(r0 + 8) * DMODEL + ng) = make_float2(v[2], v[3]);
            }
        }
    }
}

// ============ tensor-core causal flash attention (unchanged from R5) ============
#define A_QH  0u
#define A_QL  32768u
#define A_KH  65536u
#define A_KL  81920u
#define A_V   98304u
#define A_P   132096u
#define A_RM  166912u
#define A_RS  167936u
#define ATTN_SM 168960

__global__ __launch_bounds__(256, 1) void attn_mma(
    const __nv_bfloat16* __restrict__ qh, const __nv_bfloat16* __restrict__ ql,
    const __nv_bfloat16* __restrict__ kh, const __nv_bfloat16* __restrict__ kl,
    const float* __restrict__ vf,
    __nv_bfloat16* __restrict__ aoh, __nv_bfloat16* __restrict__ aol)
{
    extern __shared__ char smraw[];
    const uint32_t S0 = smem_u32(smraw);
    const int tid = threadIdx.x, w = tid >> 5, lane = tid & 31;
    const int wm = w >> 1, wn = w & 1;
    const int lrow = lane & 15, lhalf = lane >> 4;
    const int qb = blockIdx.x, bh = blockIdx.y, b = bh >> 4, h = bh & 15;
    const int q0 = qb * BQ;
    const size_t rowbase = (size_t)b * SEQ;
    const int hoff = h * DK;
    const float scale = 0.08838834764831845f;

#pragma unroll
    for (int i = 0; i < 8; ++i) {
        int c = tid + 256 * i;
        int r = c >> 4, kc = c & 15;
        uint32_t off = ((uint32_t)(kc >> 3)) * 16384u + SW128((uint32_t)(r * 128 + (kc & 7) * 16));
        const size_t gsrc = (rowbase + q0 + r) * DMODEL + hoff + kc * 8;
        cpa16(S0 + A_QH + off, qh + gsrc);
        cpa16(S0 + A_QL + off, ql + gsrc);
    }
    cpa_commit();

    float m_i[4], l_i[4], oacc[2][8][4];
#pragma unroll
    for (int ri = 0; ri < 4; ++ri) { m_i[ri] = -1e30f; l_i[ri] = 0.f; }
#pragma unroll
    for (int mt = 0; mt < 2; ++mt)
#pragma unroll
        for (int c8 = 0; c8 < 8; ++c8)
#pragma unroll
            for (int e = 0; e < 4; ++e) oacc[mt][c8][e] = 0.f;

    const int ktiles = 2 * qb + 2;
    for (int kt = 0; kt < ktiles; ++kt) {
        const int k0 = kt * BK;
        __syncthreads();
#pragma unroll
        for (int i = 0; i < 4; ++i) {
            int c = tid + 256 * i;
            int r = c >> 4, kc = c & 15;
            uint32_t off = ((uint32_t)(kc >> 3)) * 8192u + SW128((uint32_t)(r * 128 + (kc & 7) * 16));
            const size_t gsrc = (rowbase + k0 + r) * DMODEL + hoff + kc * 8;
            cpa16(S0 + A_KH + off, kh + gsrc);
            cpa16(S0 + A_KL + off, kl + gsrc);
        }
        cpa_commit();
#pragma unroll
        for (int i = 0; i < 8; ++i) {
            int c = tid + 256 * i;
            int r = c >> 5, cc = c & 31;
            float4 v4 = *(const float4*)(vf + (rowbase + k0 + r) * DMODEL + hoff + cc * 4);
            uint4 t = make_uint4(f2tf32(v4.x), f2tf32(v4.y), f2tf32(v4.z), f2tf32(v4.w));
            sts128(S0 + A_V + (uint32_t)(r * 528 + cc * 16), t);
        }
        cpa_wait0();
        __syncthreads();

        float sacc[2][4][4];
#pragma unroll
        for (int mt = 0; mt < 2; ++mt)
#pragma unroll
            for (int c = 0; c < 4; ++c)
#pragma unroll
                for (int e = 0; e < 4; ++e) sacc[mt][c][e] = 0.f;

#pragma unroll
        for (int kq = 0; kq < 8; ++kq) {
            const uint32_t koff = (uint32_t)((kq & 3) * 32 + lhalf * 16);
            const uint32_t pq = ((uint32_t)(kq >> 2)) * 16384u;
            const uint32_t pk = ((uint32_t)(kq >> 2)) * 8192u;
            uint32_t ah[2][4], al[2][4], bh_[2][4], bl_[2][4];
#pragma unroll
            for (int mt = 0; mt < 2; ++mt) {
                uint32_t off = pq + SW128((uint32_t)((wm * 32 + mt * 16 + lrow) * 128) + koff);
                ldsm4(ah[mt], S0 + A_QH + off);
                ldsm4(al[mt], S0 + A_QL + off);
            }
#pragma unroll
            for (int nt = 0; nt < 2; ++nt) {
                uint32_t off = pk + SW128((uint32_t)((wn * 32 + nt * 16 + lrow) * 128) + koff);
                ldsm4(bh_[nt], S0 + A_KH + off);
                ldsm4(bl_[nt], S0 + A_KL + off);
            }
#pragma unroll
            for (int mt = 0; mt < 2; ++mt)
#pragma unroll
                for (int nt = 0; nt < 2; ++nt)
#pragma unroll
                    for (int hf = 0; hf < 2; ++hf) {
                        float* c = sacc[mt][nt * 2 + hf];
                        mma_bf16(c, ah[mt], bh_[nt][hf], bh_[nt][hf + 2]);
                        mma_bf16(c, ah[mt], bl_[nt][hf], bl_[nt][hf + 2]);
                        mma_bf16(c, al[mt], bh_[nt][hf], bh_[nt][hf + 2]);
                    }
        }

        const bool needmask = (kt >= 2 * qb);
        float tmax[4] = { -1e30f, -1e30f, -1e30f, -1e30f };
#pragma unroll
        for (int mt = 0; mt < 2; ++mt)
#pragma unroll
            for (int c = 0; c < 4; ++c)
#pragma unroll
                for (int e = 0; e < 4; ++e) {
                    float sv = sacc[mt][c][e] * scale;
                    if (needmask) {
                        int qg = q0 + wm * 32 + mt * 16 + (lane >> 2) + ((e >> 1) << 3);
                        int kg = k0 + wn * 32 + c * 8 + ((lane & 3) << 1) + (e & 1);
                        if (kg > qg) sv = -1e30f;
                    }
                    sacc[mt][c][e] = sv;
                    int ri = mt * 2 + (e >> 1);
                    tmax[ri] = fmaxf(tmax[ri], sv);
                }
#pragma unroll
        for (int ri = 0; ri < 4; ++ri) {
            tmax[ri] = fmaxf(tmax[ri], __shfl_xor_sync(0xffffffffu, tmax[ri], 1));
            tmax[ri] = fmaxf(tmax[ri], __shfl_xor_sync(0xffffffffu, tmax[ri], 2));
        }
        if ((lane & 3) == 0) {
#pragma unroll
            for (int ri = 0; ri < 4; ++ri) {
                int rowl = wm * 32 + (ri >> 1) * 16 + (lane >> 2) + ((ri & 1) << 3);
                sts32(S0 + A_RM + (uint32_t)((wn * 128 + rowl) * 4), __float_as_uint(tmax[ri]));
            }
        }
        __syncthreads();

        float mnew[4], alpha[4];
#pragma unroll
        for (int ri = 0; ri < 4; ++ri) {
            int rowl = wm * 32 + (ri >> 1) * 16 + (lane >> 2) + ((ri & 1) << 3);
            float t0 = __uint_as_float(lds32(S0 + A_RM + (uint32_t)(rowl * 4)));
            float t1 = __uint_as_float(lds32(S0 + A_RM + (uint32_t)((128 + rowl) * 4)));
            mnew[ri] = fmaxf(m_i[ri], fmaxf(t0, t1));
            alpha[ri] = __expf(m_i[ri] - mnew[ri]);
            m_i[ri] = mnew[ri];
        }
#pragma unroll
        for (int mt = 0; mt < 2; ++mt)
#pragma unroll
            for (int c8 = 0; c8 < 8; ++c8)
#pragma unroll
                for (int e = 0; e < 4; ++e)
                    oacc[mt][c8][e] *= alpha[mt * 2 + (e >> 1)];

        float tsum[4] = { 0.f, 0.f, 0.f, 0.f };
#pragma unroll
        for (int mt = 0; mt < 2; ++mt)
#pragma unroll
            for (int c = 0; c < 4; ++c)
#pragma unroll
                for (int e = 0; e < 4; ++e) {
                    int ri = mt * 2 + (e >> 1);
                    float p = __expf(sacc[mt][c][e] - mnew[ri]);
                    tsum[ri] += p;
                    int rowl = wm * 32 + mt * 16 + (lane >> 2) + ((e >> 1) << 3);
                    int col  = wn * 32 + c * 8 + ((lane & 3) << 1) + (e & 1);
                    sts32(S0 + A_P + (uint32_t)((rowl * 68 + col) * 4), f2tf32(p));
                }
#pragma unroll
        for (int ri = 0; ri < 4; ++ri) {
            tsum[ri] += __shfl_xor_sync(0xffffffffu, tsum[ri], 1);
            tsum[ri] += __shfl_xor_sync(0xffffffffu, tsum[ri], 2);
        }
        if ((lane & 3) == 0) {
#pragma unroll
            for (int ri = 0; ri < 4; ++ri) {
                int rowl = wm * 32 + (ri >> 1) * 16 + (lane >> 2) + ((ri & 1) << 3);
                sts32(S0 + A_RS + (uint32_t)((wn * 128 + rowl) * 4), __float_as_uint(tsum[ri]));
            }
        }
        __syncthreads();
#pragma unroll
        for (int ri = 0; ri < 4; ++ri) {
            int rowl = wm * 32 + (ri >> 1) * 16 + (lane >> 2) + ((ri & 1) << 3);
            float s0 = __uint_as_float(lds32(S0 + A_RS + (uint32_t)(rowl * 4)));
            float s1 = __uint_as_float(lds32(S0 + A_RS + (uint32_t)((128 + rowl) * 4)));
            l_i[ri] = l_i[ri] * alpha[ri] + s0 + s1;
        }

#pragma unroll
        for (int ks = 0; ks < 8; ++ks) {
            uint32_t a[2][4];
#pragma unroll
            for (int mt = 0; mt < 2; ++mt) {
                uint32_t r0a = S0 + A_P +
                    (uint32_t)(((wm * 32 + mt * 16 + (lane >> 2)) * 68 + ks * 8 + (lane & 3)) * 4);
                a[mt][0] = lds32(r0a);
                a[mt][1] = lds32(r0a + 8u * 68u * 4u);
                a[mt][2] = lds32(r0a + 16u);
                a[mt][3] = lds32(r0a + 8u * 68u * 4u + 16u);
            }
#pragma unroll
            for (int c8 = 0; c8 < 8; ++c8) {
                uint32_t baddr = S0 + A_V +
                    (uint32_t)(((ks * 8 + (lane & 3)) * 132 + wn * 64 + c8 * 8 + (lane >> 2)) * 4);
                uint32_t b0 = lds32(baddr);
                uint32_t b1 = lds32(baddr + 4u * 132u * 4u);
#pragma unroll
                for (int mt = 0; mt < 2; ++mt)
                    mma_tf32(oacc[mt][c8], a[mt], b0, b1);
            }
        }
    }

#pragma unroll
    for (int mt = 0; mt < 2; ++mt)
#pragma unroll
        for (int c8 = 0; c8 < 8; ++c8)
#pragma unroll
            for (int hf = 0; hf < 2; ++hf) {
                int ri = mt * 2 + hf;
                float inv = 1.0f / l_i[ri];
                float a0 = oacc[mt][c8][hf * 2]     * inv;
                float a1 = oacc[mt][c8][hf * 2 + 1] * inv;
                int row = q0 + wm * 32 + mt * 16 + (lane >> 2) + hf * 8;
                int col = hoff + wn * 64 + c8 * 8 + ((lane & 3) << 1);
                __nv_bfloat16 h0 = __float2bfloat16(a0);
                __nv_bfloat16 h1 = __float2bfloat16(a1);
                __nv_bfloat16 l0 = __float2bfloat16(a0 - __bfloat162float(h0));
                __nv_bfloat16 l1 = __float2bfloat16(a1 - __bfloat162float(h1));
                size_t off = (rowbase + row) * DMODEL + col;
                *(__nv_bfloat162*)(aoh + off) = __nv_bfloat162(h0, h1);
                *(__nv_bfloat162*)(aol + off) = __nv_bfloat162(l0, l1);
            }
}

// ---------------------------------------------------------------------------------
extern "C" void kernel_launch(void* const* d_in, const int* in_sizes, int n_in,
                              void* d_out, int out_size)
{
    const float* x  = (const float*)d_in[0];
    const int*   tp = (const int*)  d_in[1];
    float* out = (float*)d_out;

    float* vp;
    __nv_bfloat16 *xh, *xl, *qhh, *qll, *khh, *kll, *aoh, *aol, *wh, *wl;
    cudaGetSymbolAddress((void**)&vp,  g_v);
    cudaGetSymbolAddress((void**)&xh,  g_xHi);
    cudaGetSymbolAddress((void**)&xl,  g_xLo);
    cudaGetSymbolAddress((void**)&qhh, g_qHi);
    cudaGetSymbolAddress((void**)&qll, g_qLo);
    cudaGetSymbolAddress((void**)&khh, g_kHi);
    cudaGetSymbolAddress((void**)&kll, g_kLo);
    cudaGetSymbolAddress((void**)&aoh, g_aoHi);
    cudaGetSymbolAddress((void**)&aol, g_aoLo);
    cudaGetSymbolAddress((void**)&wh,  g_wHi);
    cudaGetSymbolAddress((void**)&wl,  g_wLo);

    rope_table_kernel<<<(SEQ * (DK / 2) + 255) / 256, 256>>>(tp);

    const int NX = MTOT * DMODEL, NW = DMODEL * DMODEL;
    split_kernel<<<(NX + 255) / 256, 256>>>(x, xh, xl, NX);
    wsplit4_kernel<<<dim3((NW + 255) / 256, 4), 256>>>(
        (const float*)d_in[2], (const float*)d_in[3],
        (const float*)d_in[4], (const float*)d_in[5], wh, wl);

    cudaFuncSetAttribute(gemm2<0>, cudaFuncAttributeMaxDynamicSharedMemorySize, GSMEM);
    cudaFuncSetAttribute(gemm2<1>, cudaFuncAttributeMaxDynamicSharedMemorySize, GSMEM);
    cudaFuncSetAttribute(attn_mma, cudaFuncAttributeMaxDynamicSharedMemorySize, ATTN_SM);

    // fused QKV: N = 3*2048 over concatenated weights
    gemm2<0><<<dim3(3 * DMODEL / 256, MTOT / 128), 256, GSMEM>>>(
        xh, xl, wh, wl, vp, qhh, qll, khh, kll, nullptr);

    attn_mma<<<dim3(SEQ / BQ, BATCH * NHEADS), 256, ATTN_SM>>>(qhh, qll, khh, kll, vp, aoh, aol);

    gemm2<1><<<dim3(DMODEL / 256, MTOT / 128), 256, GSMEM>>>(
        aoh, aol, wh + 3 * (size_t)NW, wl + 3 * (size_t)NW,
        nullptr, nullptr, nullptr, nullptr, nullptr, out);
}